// round 13
// baseline (speedup 1.0000x reference)
#include <cuda_runtime.h>

#define SS 2048
#define MM 1024
#define HH 2048
#define EE 64
#define GG 4

typedef unsigned long long u64;

// Scratch (device globals; allocation-free)
__device__ float g_Gpart[4 * GG * SS * EE];    // [kc][row][e] gate partials     (8 MB)
__device__ float g_gates[GG * SS * EE];        // [row][e]                       (2 MB)
__device__ float g_Dpart[4 * EE * GG * MM];    // [sc][e][g][m] split-S partials (4 MB)
__device__ float g_Hpart[8 * EE * GG * HH];    // [mc][e][g][h] pre-ReLU partial (16 MB)
__device__ float g_Opart[16 * EE * GG * MM];   // [hc][e][g][m] partials         (16 MB)
__device__ float g_O[EE * GG * MM];            // [e][g][m]                      (1 MB)

// ---- packed fp32x2 helpers (Blackwell FFMA2; only reachable via PTX) ------
__device__ __forceinline__ void ffma2(u64& d, u64 a, u64 b) {
    asm("fma.rn.f32x2 %0, %1, %2, %0;" : "+l"(d) : "l"(a), "l"(b));
}
__device__ __forceinline__ u64 dup2(float x) {
    u64 r; asm("mov.b64 %0, {%1, %1};" : "=l"(r) : "f"(x)); return r;
}
__device__ __forceinline__ float2 unpack2(u64 v) {
    float2 r; asm("mov.b64 {%0, %1}, %2;" : "=f"(r.x), "=f"(r.y) : "l"(v)); return r;
}

// ---------------------------------------------------------------------------
// K1: Gpart[kc][row][e] = sum_{m in kc chunk} x[row][m] * wg[m][e]
// grid (128 row-tiles of 64, 4 kc of 256) x 256 thr; thread = 4r x 4e (FFMA2)
// Register-staged double-buffered fills.
// ---------------------------------------------------------------------------
__global__ __launch_bounds__(256) void k1_gates(const float* __restrict__ x,
                                                const float* __restrict__ wg) {
    __shared__ float xs[64 * 32];  // [r][k] 8 KB
    __shared__ float ws[32 * 64];  // [k][e] 8 KB
    int r0 = blockIdx.x * 64;
    int kc = blockIdx.y;  // 0..3
    int tx = threadIdx.x & 15;   // e group (4 wide)
    int ty = threadIdx.x >> 4;   // r group (4 wide)

    float4 xv[2], wv[2];
    {   // prefetch ks = 0
        int kb = kc * 256;
#pragma unroll
        for (int j = 0; j < 2; j++) {
            int i = threadIdx.x + j * 256;
            int r = i >> 3, c = i & 7;
            xv[j] = ((const float4*)(x + (size_t)(r0 + r) * MM + kb))[c];
        }
#pragma unroll
        for (int j = 0; j < 2; j++) {
            int i = threadIdx.x + j * 256;
            int k = i >> 4, c = i & 15;
            wv[j] = ((const float4*)(wg + (size_t)(kb + k) * EE))[c];
        }
    }

    u64 acc[4][2] = {};
    for (int ks = 0; ks < 8; ks++) {
        __syncthreads();
#pragma unroll
        for (int j = 0; j < 2; j++) {
            int i = threadIdx.x + j * 256;
            int r = i >> 3, c = i & 7;
            ((float4*)xs)[r * 8 + c] = xv[j];
        }
#pragma unroll
        for (int j = 0; j < 2; j++) {
            int i = threadIdx.x + j * 256;
            int k = i >> 4, c = i & 15;
            ((float4*)ws)[k * 16 + c] = wv[j];
        }
        __syncthreads();

        if (ks < 7) {
            int kb = kc * 256 + (ks + 1) * 32;
#pragma unroll
            for (int j = 0; j < 2; j++) {
                int i = threadIdx.x + j * 256;
                int r = i >> 3, c = i & 7;
                xv[j] = ((const float4*)(x + (size_t)(r0 + r) * MM + kb))[c];
            }
#pragma unroll
            for (int j = 0; j < 2; j++) {
                int i = threadIdx.x + j * 256;
                int k = i >> 4, c = i & 15;
                wv[j] = ((const float4*)(wg + (size_t)(kb + k) * EE))[c];
            }
        }

#pragma unroll
        for (int k = 0; k < 32; k++) {
            u64 w01 = *(const u64*)(ws + k * 64 + tx * 4);
            u64 w23 = *(const u64*)(ws + k * 64 + tx * 4 + 2);
#pragma unroll
            for (int ii = 0; ii < 4; ii++) {
                u64 xd = dup2(xs[(ty * 4 + ii) * 32 + k]);
                ffma2(acc[ii][0], xd, w01);
                ffma2(acc[ii][1], xd, w23);
            }
        }
    }
#pragma unroll
    for (int ii = 0; ii < 4; ii++) {
        float2 a = unpack2(acc[ii][0]), b = unpack2(acc[ii][1]);
        float4 v = make_float4(a.x, a.y, b.x, b.y);
        *((float4*)(g_Gpart + ((size_t)kc * GG * SS * EE) +
                    (size_t)(r0 + ty * 4 + ii) * EE + tx * 4)) = v;
    }
}

// K1b: gates = sum of 4 K partials. 131072 float4 -> 512 blocks x 256 thr.
__global__ __launch_bounds__(256) void k1b_reduce() {
    int idx = blockIdx.x * 256 + threadIdx.x;
    const float4* p = (const float4*)g_Gpart;
    float4 s = __ldcs(p + idx);
#pragma unroll
    for (int kc = 1; kc < 4; kc++) {
        float4 v = __ldcs(p + (size_t)kc * (GG * SS * EE / 4) + idx);
        s.x += v.x; s.y += v.y; s.z += v.z; s.w += v.w;
    }
    ((float4*)g_gates)[idx] = s;
}

// ---------------------------------------------------------------------------
// K2: Dpart[sc][e][g][m] = sum_{s in chunk sc} gates[g,s,e] * x[g,s,m]
// grid (16 m-tiles, 4 g, 4 s-chunks) x 256 thr; thread = 4e x 4m (FFMA2)
// Register-staged double-buffered fills.
// ---------------------------------------------------------------------------
__global__ __launch_bounds__(256) void k2_dispatch(const float* __restrict__ x) {
    __shared__ float gs[64 * 64];   // [s][e] 16 KB
    __shared__ float xsm[64 * 64];  // [s][m] 16 KB
    int m0 = blockIdx.x * 64;
    int g  = blockIdx.y;
    int sc = blockIdx.z;
    int tx = threadIdx.x & 15;   // m group (4 wide)
    int ty = threadIdx.x >> 4;   // e group (4 wide)

    float4 gv[4], xv[4];
    {   // prefetch tile 0
        int s0 = sc * 512;
#pragma unroll
        for (int j = 0; j < 4; j++) {
            int i = threadIdx.x + j * 256;
            int ss = i >> 4, c = i & 15;
            gv[j] = ((const float4*)(g_gates + (size_t)(g * SS + s0 + ss) * EE))[c];
            xv[j] = ((const float4*)(x + (size_t)(g * SS + s0 + ss) * MM + m0))[c];
        }
    }

    u64 acc[4][2] = {};
    for (int t = 0; t < 8; t++) {
        __syncthreads();
#pragma unroll
        for (int j = 0; j < 4; j++) {
            int i = threadIdx.x + j * 256;
            int ss = i >> 4, c = i & 15;
            ((float4*)gs)[ss * 16 + c] = gv[j];
            ((float4*)xsm)[ss * 16 + c] = xv[j];
        }
        __syncthreads();

        if (t < 7) {
            int s0 = sc * 512 + (t + 1) * 64;
#pragma unroll
            for (int j = 0; j < 4; j++) {
                int i = threadIdx.x + j * 256;
                int ss = i >> 4, c = i & 15;
                gv[j] = ((const float4*)(g_gates + (size_t)(g * SS + s0 + ss) * EE))[c];
                xv[j] = ((const float4*)(x + (size_t)(g * SS + s0 + ss) * MM + m0))[c];
            }
        }

#pragma unroll 8
        for (int ss = 0; ss < 64; ss++) {
            float4 ge = *(const float4*)(gs + ss * 64 + ty * 4);
            u64 x01 = *(const u64*)(xsm + ss * 64 + tx * 4);
            u64 x23 = *(const u64*)(xsm + ss * 64 + tx * 4 + 2);
            u64 g0 = dup2(ge.x), g1 = dup2(ge.y), g2 = dup2(ge.z), g3 = dup2(ge.w);
            ffma2(acc[0][0], g0, x01); ffma2(acc[0][1], g0, x23);
            ffma2(acc[1][0], g1, x01); ffma2(acc[1][1], g1, x23);
            ffma2(acc[2][0], g2, x01); ffma2(acc[2][1], g2, x23);
            ffma2(acc[3][0], g3, x01); ffma2(acc[3][1], g3, x23);
        }
    }
#pragma unroll
    for (int ii = 0; ii < 4; ii++) {
        int ee = ty * 4 + ii;
        float2 a = unpack2(acc[ii][0]), b = unpack2(acc[ii][1]);
        float4 v = make_float4(a.x, a.y, b.x, b.y);
        *((float4*)(g_Dpart + (((size_t)sc * EE + ee) * GG + g) * MM + m0 + tx * 4)) = v;
    }
}

// ---------------------------------------------------------------------------
// K3: Hpart[mc][e][g][h] = sum_{m in chunk mc(128)} D[e,g,m] * wi[e][m][h]
// grid (64 e, 2 h-halves, 8 m-chunks) = 1024 blocks x 256 thr. Streams wi once
// (__ldcs). Dpart reads stay default-cached (read twice: once per hb block).
// ---------------------------------------------------------------------------
__global__ __launch_bounds__(256) void k3_ffn1(const float* __restrict__ wi) {
    __shared__ float ds[GG * 128];  // [g][m-local] 2 KB
    int e  = blockIdx.x;
    int hb = blockIdx.y;            // 0..1
    int mc = blockIdx.z;            // 0..7
    int h0 = hb * 1024 + threadIdx.x * 4;

    for (int i = threadIdx.x; i < GG * 128 / 4; i += 256) {
        int g = i >> 5, c = i & 31;
        size_t base = ((size_t)e * GG + g) * MM + mc * 128 + c * 4;
        const float4 a = *(const float4*)(g_Dpart + (size_t)0 * EE * GG * MM + base);
        const float4 b = *(const float4*)(g_Dpart + (size_t)1 * EE * GG * MM + base);
        const float4 cc = *(const float4*)(g_Dpart + (size_t)2 * EE * GG * MM + base);
        const float4 d = *(const float4*)(g_Dpart + (size_t)3 * EE * GG * MM + base);
        ((float4*)ds)[i] = make_float4(a.x + b.x + cc.x + d.x, a.y + b.y + cc.y + d.y,
                                       a.z + b.z + cc.z + d.z, a.w + b.w + cc.w + d.w);
    }
    __syncthreads();

    float acc[4][4] = {};
    const float4* w4 = (const float4*)(wi + (size_t)e * MM * HH);
#pragma unroll 8
    for (int mi = 0; mi < 128; mi++) {
        int m = mc * 128 + mi;
        float4 w = __ldcs(w4 + (((size_t)m * HH + h0) >> 2));
#pragma unroll
        for (int g = 0; g < 4; g++) {
            float d = ds[g * 128 + mi];
            acc[g][0] += d * w.x;
            acc[g][1] += d * w.y;
            acc[g][2] += d * w.z;
            acc[g][3] += d * w.w;
        }
    }
#pragma unroll
    for (int g = 0; g < 4; g++) {
        float4 v = make_float4(acc[g][0], acc[g][1], acc[g][2], acc[g][3]);
        *((float4*)(g_Hpart + (((size_t)mc * EE + e) * GG + g) * HH + h0)) = v;
    }
}

// ---------------------------------------------------------------------------
// K4: Opart[hc][e][g][m] = sum_{h in chunk hc(128)} relu(Hh[e,g,h]) * wo[e][h][m]
// grid (64 e, 16 h-chunks) = 1024 blocks x 256 thr. Streams wo once (__ldcs).
// Hpart is read exactly once chip-wide -> __ldcs on the fill too.
// ---------------------------------------------------------------------------
__global__ __launch_bounds__(256) void k4_ffn2(const float* __restrict__ wo) {
    __shared__ float hs[GG * 128];  // [g][h-local] 2 KB
    int e  = blockIdx.x;
    int hc = blockIdx.y;            // 0..15
    int m0 = threadIdx.x * 4;

    for (int i = threadIdx.x; i < GG * 128 / 4; i += 256) {
        int g = i >> 5, c = i & 31;
        size_t base = ((size_t)e * GG + g) * HH + hc * 128 + c * 4;
        float4 s = __ldcs((const float4*)(g_Hpart + base));
#pragma unroll
        for (int mc = 1; mc < 8; mc++) {
            const float4 v = __ldcs((const float4*)(g_Hpart + (size_t)mc * EE * GG * HH + base));
            s.x += v.x; s.y += v.y; s.z += v.z; s.w += v.w;
        }
        ((float4*)hs)[i] = make_float4(fmaxf(s.x, 0.f), fmaxf(s.y, 0.f),
                                       fmaxf(s.z, 0.f), fmaxf(s.w, 0.f));
    }
    __syncthreads();

    float acc[4][4] = {};
    const float4* w4 = (const float4*)(wo + (size_t)e * HH * MM);
#pragma unroll 8
    for (int hi = 0; hi < 128; hi++) {
        int h = hc * 128 + hi;
        float4 w = __ldcs(w4 + (((size_t)h * MM + m0) >> 2));
#pragma unroll
        for (int g = 0; g < 4; g++) {
            float hv = hs[g * 128 + hi];
            acc[g][0] += hv * w.x;
            acc[g][1] += hv * w.y;
            acc[g][2] += hv * w.z;
            acc[g][3] += hv * w.w;
        }
    }
#pragma unroll
    for (int g = 0; g < 4; g++) {
        float4 v = make_float4(acc[g][0], acc[g][1], acc[g][2], acc[g][3]);
        *((float4*)(g_Opart + (((size_t)hc * EE + e) * GG + g) * MM + m0)) = v;
    }
}

// ---------------------------------------------------------------------------
// K4b: O = sum over 16 h-chunk partials. 65536 float4 -> 256 blocks x 256 thr.
// ---------------------------------------------------------------------------
__global__ __launch_bounds__(256) void k4b_reduce() {
    int idx = blockIdx.x * 256 + threadIdx.x;
    const float4* p = (const float4*)g_Opart;
    float4 s = __ldcs(p + idx);
#pragma unroll
    for (int hc = 1; hc < 16; hc++) {
        float4 v = __ldcs(p + (size_t)hc * (EE * GG * MM / 4) + idx);
        s.x += v.x; s.y += v.y; s.z += v.z; s.w += v.w;
    }
    ((float4*)g_O)[idx] = s;
}

// ---------------------------------------------------------------------------
// K5: out[row][m] = 64 * sum_e gates[row][e] * O[e][g][m]   (FFMA2)
// grid (4 m-blocks of 256, 256 row-blocks of 32) x 256 thr; 8r x 4m per thread
// gates staged PRE-DUPLICATED (u64) in SMEM at fill time; per-warp gsm loads
// are uniform-address (single ty per warp) -> broadcast LDS.64, no conflict.
// Inner loop: 10 LDS.64 + 16 FFMA2 (was 34 issue slots per 16 FFMA2).
// ---------------------------------------------------------------------------
__global__ __launch_bounds__(256) void k5_combine(float* __restrict__ out) {
    __shared__ u64 gsm[32 * 64];     // [r][e] duplicated, 16 KB
    __shared__ float osm[16 * 256];  // [e-chunk][m] 16 KB
    int m0 = blockIdx.x * 256;
    int row0 = blockIdx.y * 32;
    int g = row0 >> 11;              // 2048 rows per group; 32 | 2048
    int tx = threadIdx.x & 63;       // m (4 wide)
    int ty = threadIdx.x >> 6;       // row group (8 rows)

    for (int i = threadIdx.x; i < 32 * 16; i += 256) {  // 512 float4, 2/thread
        int r = i >> 4, c = i & 15;
        float4 gq = ((const float4*)(g_gates + (size_t)(row0 + r) * EE))[c];
        int base = r * 64 + c * 4;
        gsm[base + 0] = dup2(gq.x);
        gsm[base + 1] = dup2(gq.y);
        gsm[base + 2] = dup2(gq.z);
        gsm[base + 3] = dup2(gq.w);
    }

    u64 acc[8][2] = {};
    for (int ec = 0; ec < 4; ec++) {
        __syncthreads();
        for (int i = threadIdx.x; i < 16 * 64; i += 256) {
            int eI = i >> 6, c = i & 63;
            ((float4*)osm)[i] =
                ((const float4*)(g_O + (size_t)((ec * 16 + eI) * GG + g) * MM + m0))[c];
        }
        __syncthreads();
#pragma unroll
        for (int eI = 0; eI < 16; eI++) {
            u64 o01 = *(const u64*)(osm + eI * 256 + tx * 4);
            u64 o23 = *(const u64*)(osm + eI * 256 + tx * 4 + 2);
            int e = ec * 16 + eI;
#pragma unroll
            for (int ii = 0; ii < 8; ii++) {
                u64 gd = gsm[(ty * 8 + ii) * 64 + e];
                ffma2(acc[ii][0], gd, o01);
                ffma2(acc[ii][1], gd, o23);
            }
        }
    }
#pragma unroll
    for (int ii = 0; ii < 8; ii++) {
        int row = row0 + ty * 8 + ii;
        float2 a = unpack2(acc[ii][0]), b = unpack2(acc[ii][1]);
        float4 v = make_float4(a.x * 64.f, a.y * 64.f, b.x * 64.f, b.y * 64.f);
        ((float4*)(out + (size_t)row * MM + m0))[tx] = v;
    }
}

// ---------------------------------------------------------------------------
extern "C" void kernel_launch(void* const* d_in, const int* in_sizes, int n_in,
                              void* d_out, int out_size) {
    const float* x  = (const float*)d_in[0];  // (8192, 1024)
    const float* wg = (const float*)d_in[1];  // (1024, 64)
    const float* wi = (const float*)d_in[2];  // (64, 1024, 2048)
    const float* wo = (const float*)d_in[3];  // (64, 2048, 1024)
    float* out = (float*)d_out;

    k1_gates<<<dim3(128, 4), 256>>>(x, wg);
    k1b_reduce<<<512, 256>>>();
    k2_dispatch<<<dim3(16, 4, 4), 256>>>(x);
    k3_ffn1<<<dim3(64, 2, 8), 256>>>(wi);
    k4_ffn2<<<dim3(64, 16), 256>>>(wo);
    k4b_reduce<<<256, 256>>>();
    k5_combine<<<dim3(4, 256), 256>>>(out);
}

// round 14
// speedup vs baseline: 1.0605x; 1.0605x over previous
#include <cuda_runtime.h>

#define SS 2048
#define MM 1024
#define HH 2048
#define EE 64
#define GG 4

typedef unsigned long long u64;

// Scratch (device globals; allocation-free)
__device__ float g_Gpart[4 * GG * SS * EE];    // [kc][row][e] gate partials     (8 MB)
__device__ float g_gates[GG * SS * EE];        // [row][e]                       (2 MB)
__device__ float g_Dpart[4 * EE * GG * MM];    // [sc][e][g][m] split-S partials (4 MB)
__device__ float g_Hpart[8 * EE * GG * HH];    // [mc][e][g][h] pre-ReLU partial (16 MB)
__device__ float g_Opart[16 * EE * GG * MM];   // [hc][e][g][m] partials         (16 MB)
__device__ float g_O[EE * GG * MM];            // [e][g][m]                      (1 MB)

// ---- packed fp32x2 helpers (Blackwell FFMA2; only reachable via PTX) ------
__device__ __forceinline__ void ffma2(u64& d, u64 a, u64 b) {
    asm("fma.rn.f32x2 %0, %1, %2, %0;" : "+l"(d) : "l"(a), "l"(b));
}
__device__ __forceinline__ u64 dup2(float x) {
    u64 r; asm("mov.b64 %0, {%1, %1};" : "=l"(r) : "f"(x)); return r;
}
__device__ __forceinline__ float2 unpack2(u64 v) {
    float2 r; asm("mov.b64 {%0, %1}, %2;" : "=f"(r.x), "=f"(r.y) : "l"(v)); return r;
}

// ---------------------------------------------------------------------------
// K1: Gpart[kc][row][e] = sum_{m in kc chunk} x[row][m] * wg[m][e]
// grid (128 row-tiles of 64, 4 kc of 256) x 256 thr; thread = 4r x 4e (FFMA2)
// Register-staged double-buffered fills.
// ---------------------------------------------------------------------------
__global__ __launch_bounds__(256) void k1_gates(const float* __restrict__ x,
                                                const float* __restrict__ wg) {
    __shared__ float xs[64 * 32];  // [r][k] 8 KB
    __shared__ float ws[32 * 64];  // [k][e] 8 KB
    int r0 = blockIdx.x * 64;
    int kc = blockIdx.y;  // 0..3
    int tx = threadIdx.x & 15;   // e group (4 wide)
    int ty = threadIdx.x >> 4;   // r group (4 wide)

    float4 xv[2], wv[2];
    {   // prefetch ks = 0
        int kb = kc * 256;
#pragma unroll
        for (int j = 0; j < 2; j++) {
            int i = threadIdx.x + j * 256;
            int r = i >> 3, c = i & 7;
            xv[j] = ((const float4*)(x + (size_t)(r0 + r) * MM + kb))[c];
        }
#pragma unroll
        for (int j = 0; j < 2; j++) {
            int i = threadIdx.x + j * 256;
            int k = i >> 4, c = i & 15;
            wv[j] = ((const float4*)(wg + (size_t)(kb + k) * EE))[c];
        }
    }

    u64 acc[4][2] = {};
    for (int ks = 0; ks < 8; ks++) {
        __syncthreads();
#pragma unroll
        for (int j = 0; j < 2; j++) {
            int i = threadIdx.x + j * 256;
            int r = i >> 3, c = i & 7;
            ((float4*)xs)[r * 8 + c] = xv[j];
        }
#pragma unroll
        for (int j = 0; j < 2; j++) {
            int i = threadIdx.x + j * 256;
            int k = i >> 4, c = i & 15;
            ((float4*)ws)[k * 16 + c] = wv[j];
        }
        __syncthreads();

        if (ks < 7) {
            int kb = kc * 256 + (ks + 1) * 32;
#pragma unroll
            for (int j = 0; j < 2; j++) {
                int i = threadIdx.x + j * 256;
                int r = i >> 3, c = i & 7;
                xv[j] = ((const float4*)(x + (size_t)(r0 + r) * MM + kb))[c];
            }
#pragma unroll
            for (int j = 0; j < 2; j++) {
                int i = threadIdx.x + j * 256;
                int k = i >> 4, c = i & 15;
                wv[j] = ((const float4*)(wg + (size_t)(kb + k) * EE))[c];
            }
        }

#pragma unroll
        for (int k = 0; k < 32; k++) {
            u64 w01 = *(const u64*)(ws + k * 64 + tx * 4);
            u64 w23 = *(const u64*)(ws + k * 64 + tx * 4 + 2);
#pragma unroll
            for (int ii = 0; ii < 4; ii++) {
                u64 xd = dup2(xs[(ty * 4 + ii) * 32 + k]);
                ffma2(acc[ii][0], xd, w01);
                ffma2(acc[ii][1], xd, w23);
            }
        }
    }
#pragma unroll
    for (int ii = 0; ii < 4; ii++) {
        float2 a = unpack2(acc[ii][0]), b = unpack2(acc[ii][1]);
        float4 v = make_float4(a.x, a.y, b.x, b.y);
        *((float4*)(g_Gpart + ((size_t)kc * GG * SS * EE) +
                    (size_t)(r0 + ty * 4 + ii) * EE + tx * 4)) = v;
    }
}

// K1b: gates = sum of 4 K partials. 131072 float4 -> 512 blocks x 256 thr.
__global__ __launch_bounds__(256) void k1b_reduce() {
    int idx = blockIdx.x * 256 + threadIdx.x;
    const float4* p = (const float4*)g_Gpart;
    float4 s = __ldcs(p + idx);
#pragma unroll
    for (int kc = 1; kc < 4; kc++) {
        float4 v = __ldcs(p + (size_t)kc * (GG * SS * EE / 4) + idx);
        s.x += v.x; s.y += v.y; s.z += v.z; s.w += v.w;
    }
    ((float4*)g_gates)[idx] = s;
}

// ---------------------------------------------------------------------------
// K2: Dpart[sc][e][g][m] = sum_{s in chunk sc} gates[g,s,e] * x[g,s,m]
// grid (16 m-tiles, 4 g, 4 s-chunks) x 256 thr; thread = 4e x 4m (FFMA2)
// Register-staged double-buffered fills.
// ---------------------------------------------------------------------------
__global__ __launch_bounds__(256) void k2_dispatch(const float* __restrict__ x) {
    __shared__ float gs[64 * 64];   // [s][e] 16 KB
    __shared__ float xsm[64 * 64];  // [s][m] 16 KB
    int m0 = blockIdx.x * 64;
    int g  = blockIdx.y;
    int sc = blockIdx.z;
    int tx = threadIdx.x & 15;   // m group (4 wide)
    int ty = threadIdx.x >> 4;   // e group (4 wide)

    float4 gv[4], xv[4];
    {   // prefetch tile 0
        int s0 = sc * 512;
#pragma unroll
        for (int j = 0; j < 4; j++) {
            int i = threadIdx.x + j * 256;
            int ss = i >> 4, c = i & 15;
            gv[j] = ((const float4*)(g_gates + (size_t)(g * SS + s0 + ss) * EE))[c];
            xv[j] = ((const float4*)(x + (size_t)(g * SS + s0 + ss) * MM + m0))[c];
        }
    }

    u64 acc[4][2] = {};
    for (int t = 0; t < 8; t++) {
        __syncthreads();
#pragma unroll
        for (int j = 0; j < 4; j++) {
            int i = threadIdx.x + j * 256;
            int ss = i >> 4, c = i & 15;
            ((float4*)gs)[ss * 16 + c] = gv[j];
            ((float4*)xsm)[ss * 16 + c] = xv[j];
        }
        __syncthreads();

        if (t < 7) {
            int s0 = sc * 512 + (t + 1) * 64;
#pragma unroll
            for (int j = 0; j < 4; j++) {
                int i = threadIdx.x + j * 256;
                int ss = i >> 4, c = i & 15;
                gv[j] = ((const float4*)(g_gates + (size_t)(g * SS + s0 + ss) * EE))[c];
                xv[j] = ((const float4*)(x + (size_t)(g * SS + s0 + ss) * MM + m0))[c];
            }
        }

#pragma unroll 8
        for (int ss = 0; ss < 64; ss++) {
            float4 ge = *(const float4*)(gs + ss * 64 + ty * 4);
            u64 x01 = *(const u64*)(xsm + ss * 64 + tx * 4);
            u64 x23 = *(const u64*)(xsm + ss * 64 + tx * 4 + 2);
            u64 g0 = dup2(ge.x), g1 = dup2(ge.y), g2 = dup2(ge.z), g3 = dup2(ge.w);
            ffma2(acc[0][0], g0, x01); ffma2(acc[0][1], g0, x23);
            ffma2(acc[1][0], g1, x01); ffma2(acc[1][1], g1, x23);
            ffma2(acc[2][0], g2, x01); ffma2(acc[2][1], g2, x23);
            ffma2(acc[3][0], g3, x01); ffma2(acc[3][1], g3, x23);
        }
    }
#pragma unroll
    for (int ii = 0; ii < 4; ii++) {
        int ee = ty * 4 + ii;
        float2 a = unpack2(acc[ii][0]), b = unpack2(acc[ii][1]);
        float4 v = make_float4(a.x, a.y, b.x, b.y);
        *((float4*)(g_Dpart + (((size_t)sc * EE + ee) * GG + g) * MM + m0 + tx * 4)) = v;
    }
}

// ---------------------------------------------------------------------------
// K3: Hpart[mc][e][g][h] = sum_{m in chunk mc(128)} D[e,g,m] * wi[e][m][h]
// grid (64 e, 2 h-halves, 8 m-chunks) = 1024 blocks x 256 thr. Streams wi once
// (__ldcs). unroll 4 to cut regs -> 5 blocks/SM residency.
// ---------------------------------------------------------------------------
__global__ __launch_bounds__(256) void k3_ffn1(const float* __restrict__ wi) {
    __shared__ float ds[GG * 128];  // [g][m-local] 2 KB
    int e  = blockIdx.x;
    int hb = blockIdx.y;            // 0..1
    int mc = blockIdx.z;            // 0..7
    int h0 = hb * 1024 + threadIdx.x * 4;

    for (int i = threadIdx.x; i < GG * 128 / 4; i += 256) {
        int g = i >> 5, c = i & 31;
        size_t base = ((size_t)e * GG + g) * MM + mc * 128 + c * 4;
        const float4 a = *(const float4*)(g_Dpart + (size_t)0 * EE * GG * MM + base);
        const float4 b = *(const float4*)(g_Dpart + (size_t)1 * EE * GG * MM + base);
        const float4 cc = *(const float4*)(g_Dpart + (size_t)2 * EE * GG * MM + base);
        const float4 d = *(const float4*)(g_Dpart + (size_t)3 * EE * GG * MM + base);
        ((float4*)ds)[i] = make_float4(a.x + b.x + cc.x + d.x, a.y + b.y + cc.y + d.y,
                                       a.z + b.z + cc.z + d.z, a.w + b.w + cc.w + d.w);
    }
    __syncthreads();

    float acc[4][4] = {};
    const float4* w4 = (const float4*)(wi + (size_t)e * MM * HH);
#pragma unroll 4
    for (int mi = 0; mi < 128; mi++) {
        int m = mc * 128 + mi;
        float4 w = __ldcs(w4 + (((size_t)m * HH + h0) >> 2));
#pragma unroll
        for (int g = 0; g < 4; g++) {
            float d = ds[g * 128 + mi];
            acc[g][0] += d * w.x;
            acc[g][1] += d * w.y;
            acc[g][2] += d * w.z;
            acc[g][3] += d * w.w;
        }
    }
#pragma unroll
    for (int g = 0; g < 4; g++) {
        float4 v = make_float4(acc[g][0], acc[g][1], acc[g][2], acc[g][3]);
        *((float4*)(g_Hpart + (((size_t)mc * EE + e) * GG + g) * HH + h0)) = v;
    }
}

// ---------------------------------------------------------------------------
// K4: Opart[hc][e][g][m] = sum_{h in chunk hc(128)} relu(Hh[e,g,h]) * wo[e][h][m]
// grid (64 e, 16 h-chunks) = 1024 blocks x 256 thr. Streams wo once (__ldcs).
// unroll 4 to cut regs -> 5 blocks/SM residency.
// ---------------------------------------------------------------------------
__global__ __launch_bounds__(256) void k4_ffn2(const float* __restrict__ wo) {
    __shared__ float hs[GG * 128];  // [g][h-local] 2 KB
    int e  = blockIdx.x;
    int hc = blockIdx.y;            // 0..15
    int m0 = threadIdx.x * 4;

    for (int i = threadIdx.x; i < GG * 128 / 4; i += 256) {
        int g = i >> 5, c = i & 31;
        size_t base = ((size_t)e * GG + g) * HH + hc * 128 + c * 4;
        float4 s = __ldcs((const float4*)(g_Hpart + base));
#pragma unroll
        for (int mc = 1; mc < 8; mc++) {
            const float4 v = __ldcs((const float4*)(g_Hpart + (size_t)mc * EE * GG * HH + base));
            s.x += v.x; s.y += v.y; s.z += v.z; s.w += v.w;
        }
        ((float4*)hs)[i] = make_float4(fmaxf(s.x, 0.f), fmaxf(s.y, 0.f),
                                       fmaxf(s.z, 0.f), fmaxf(s.w, 0.f));
    }
    __syncthreads();

    float acc[4][4] = {};
    const float4* w4 = (const float4*)(wo + (size_t)e * HH * MM);
#pragma unroll 4
    for (int hi = 0; hi < 128; hi++) {
        int h = hc * 128 + hi;
        float4 w = __ldcs(w4 + (((size_t)h * MM + m0) >> 2));
#pragma unroll
        for (int g = 0; g < 4; g++) {
            float hv = hs[g * 128 + hi];
            acc[g][0] += hv * w.x;
            acc[g][1] += hv * w.y;
            acc[g][2] += hv * w.z;
            acc[g][3] += hv * w.w;
        }
    }
#pragma unroll
    for (int g = 0; g < 4; g++) {
        float4 v = make_float4(acc[g][0], acc[g][1], acc[g][2], acc[g][3]);
        *((float4*)(g_Opart + (((size_t)hc * EE + e) * GG + g) * MM + m0)) = v;
    }
}

// ---------------------------------------------------------------------------
// K4b: O = sum over 16 h-chunk partials. 65536 float4 -> 256 blocks x 256 thr.
// ---------------------------------------------------------------------------
__global__ __launch_bounds__(256) void k4b_reduce() {
    int idx = blockIdx.x * 256 + threadIdx.x;
    const float4* p = (const float4*)g_Opart;
    float4 s = __ldcs(p + idx);
#pragma unroll
    for (int hc = 1; hc < 16; hc++) {
        float4 v = __ldcs(p + (size_t)hc * (EE * GG * MM / 4) + idx);
        s.x += v.x; s.y += v.y; s.z += v.z; s.w += v.w;
    }
    ((float4*)g_O)[idx] = s;
}

// ---------------------------------------------------------------------------
// K5: out[row][m] = 64 * sum_e gates[row][e] * O[e][g][m]   (FFMA2)
// grid (4 m-blocks of 256, 256 row-blocks of 32) x 256 thr; 8r x 4m per thread
// e processed in 4 chunks of 16 (osm 16 KB); gsm 8 KB.  (R12 form)
// ---------------------------------------------------------------------------
__global__ __launch_bounds__(256) void k5_combine(float* __restrict__ out) {
    __shared__ float gsm[32 * 64];   // [r][e] 8 KB
    __shared__ float osm[16 * 256];  // [e-chunk][m] 16 KB
    int m0 = blockIdx.x * 256;
    int row0 = blockIdx.y * 32;
    int g = row0 >> 11;              // 2048 rows per group; 32 | 2048
    int tx = threadIdx.x & 63;       // m (4 wide)
    int ty = threadIdx.x >> 6;       // row group (8 rows)

    for (int i = threadIdx.x; i < 32 * 16; i += 256)
        ((float4*)gsm)[i] = ((const float4*)(g_gates + (size_t)row0 * EE))[i];

    u64 acc[8][2] = {};
    for (int ec = 0; ec < 4; ec++) {
        __syncthreads();
        for (int i = threadIdx.x; i < 16 * 64; i += 256) {
            int eI = i >> 6, c = i & 63;
            ((float4*)osm)[i] =
                ((const float4*)(g_O + (size_t)((ec * 16 + eI) * GG + g) * MM + m0))[c];
        }
        __syncthreads();
#pragma unroll
        for (int eI = 0; eI < 16; eI++) {
            u64 o01 = *(const u64*)(osm + eI * 256 + tx * 4);
            u64 o23 = *(const u64*)(osm + eI * 256 + tx * 4 + 2);
            int e = ec * 16 + eI;
#pragma unroll
            for (int ii = 0; ii < 8; ii++) {
                u64 gd = dup2(gsm[(ty * 8 + ii) * 64 + e]);
                ffma2(acc[ii][0], gd, o01);
                ffma2(acc[ii][1], gd, o23);
            }
        }
    }
#pragma unroll
    for (int ii = 0; ii < 8; ii++) {
        int row = row0 + ty * 8 + ii;
        float2 a = unpack2(acc[ii][0]), b = unpack2(acc[ii][1]);
        float4 v = make_float4(a.x * 64.f, a.y * 64.f, b.x * 64.f, b.y * 64.f);
        ((float4*)(out + (size_t)row * MM + m0))[tx] = v;
    }
}

// ---------------------------------------------------------------------------
extern "C" void kernel_launch(void* const* d_in, const int* in_sizes, int n_in,
                              void* d_out, int out_size) {
    const float* x  = (const float*)d_in[0];  // (8192, 1024)
    const float* wg = (const float*)d_in[1];  // (1024, 64)
    const float* wi = (const float*)d_in[2];  // (64, 1024, 2048)
    const float* wo = (const float*)d_in[3];  // (64, 2048, 1024)
    float* out = (float*)d_out;

    k1_gates<<<dim3(128, 4), 256>>>(x, wg);
    k1b_reduce<<<512, 256>>>();
    k2_dispatch<<<dim3(16, 4, 4), 256>>>(x);
    k3_ffn1<<<dim3(64, 2, 8), 256>>>(wi);
    k4_ffn2<<<dim3(64, 16), 256>>>(wo);
    k4b_reduce<<<256, 256>>>();
    k5_combine<<<dim3(4, 256), 256>>>(out);
}